// round 4
// baseline (speedup 1.0000x reference)
#include <cuda_runtime.h>
#include <cuda_bf16.h>
#include <cstdint>

// Problem constants
#define BS      32
#define SEQ_LEN 4096
#define HIDDEN  1024

// ---------------------------------------------------------------------------
// Threefry-2x32-20 core — verified against Random123 KAT:
//   threefry2x32(key=(0,0), ctr=(0,0)) == (0x6B200159, 0x99BA4EFE)
// ---------------------------------------------------------------------------
__device__ __forceinline__ uint32_t rotl32(uint32_t x, int r) {
    return (x << r) | (x >> (32 - r));
}

__device__ __forceinline__ void threefry2x32(uint32_t k0, uint32_t k1,
                                             uint32_t x0, uint32_t x1,
                                             uint32_t& o0, uint32_t& o1) {
    const uint32_t ks2 = k0 ^ k1 ^ 0x1BD11BDAu;
    uint32_t ks[3] = {k0, k1, ks2};
    const int R[2][4] = {{13, 15, 26, 6}, {17, 29, 16, 24}};

    x0 += ks[0];
    x1 += ks[1];
#pragma unroll
    for (int i = 0; i < 5; i++) {
#pragma unroll
        for (int j = 0; j < 4; j++) {
            x0 += x1;
            x1 = rotl32(x1, R[i & 1][j]);
            x1 ^= x0;
        }
        x0 += ks[(i + 1) % 3];
        x1 += ks[(i + 2) % 3] + (uint32_t)(i + 1);
    }
    o0 = x0;
    o1 = x1;
}

// JAX partitionable-threefry random_bits (default since JAX ~0.4.36):
//   counts = iota(uint64) flat row-major; per element i:
//   (bits1, bits2) = threefry2x32(key, hi32(i), lo32(i))
//   bit_width 64 -> (bits1 << 32) | bits2
//   bit_width 32 -> bits1 ^ bits2          <-- the fix (was: bits2)
__device__ __forceinline__ uint32_t jax_random_bits_partitionable(uint32_t i) {
    uint32_t o0, o1;
    threefry2x32(0u, 42u, 0u, i, o0, o1);
    return o0 ^ o1;
}

// ---------------------------------------------------------------------------
// One block per batch row: reduce mask -> n_valid, then 1024 threads each
// compute one output column.
// ---------------------------------------------------------------------------
__global__ __launch_bounds__(1024)
void condensed_embracement_kernel(const float* __restrict__ tokens,
                                  const int* __restrict__ mask,
                                  float* __restrict__ out) {
    const int b   = blockIdx.x;   // 0..31
    const int e   = threadIdx.x;  // 0..1023

    // ---- mask row sum (mask is prefix-form: 1..1 0..0, sum == argmin/first0)
    __shared__ int warp_sums[32];
    const int* mrow = mask + b * SEQ_LEN;
    int s = 0;
#pragma unroll
    for (int k = 0; k < SEQ_LEN / 1024; k++)   // 4 elements per thread
        s += mrow[e + k * 1024];
    // warp reduce
#pragma unroll
    for (int off = 16; off > 0; off >>= 1)
        s += __shfl_xor_sync(0xFFFFFFFFu, s, off);
    if ((e & 31) == 0) warp_sums[e >> 5] = s;
    __syncthreads();
    if (e < 32) {
        int v = warp_sums[e];
#pragma unroll
        for (int off = 16; off > 0; off >>= 1)
            v += __shfl_xor_sync(0xFFFFFFFFu, v, off);
        if (e == 0) warp_sums[0] = v;
    }
    __syncthreads();
    const int prefix  = warp_sums[0];
    const int n_valid = max(prefix - 1, 1);

    // ---- uniform sample for (b, e), bit-exact vs jax.random.uniform(key(42))
    const uint32_t i = (uint32_t)(b * HIDDEN + e);   // flat row-major counter
    const uint32_t bits = jax_random_bits_partitionable(i);
    const float u = __uint_as_float((bits >> 9) | 0x3F800000u) - 1.0f;

    // idx = min(int(u * float(n_valid)), n_valid - 1)   (truncation, u >= 0)
    int idx = (int)(u * (float)n_valid);
    idx = min(idx, n_valid - 1);

    // ---- gather
    out[i] = tokens[((size_t)b * SEQ_LEN + (size_t)idx) * HIDDEN + e];
}

extern "C" void kernel_launch(void* const* d_in, const int* in_sizes, int n_in,
                              void* d_out, int out_size) {
    // Disambiguate inputs by element count (robust to metadata ordering):
    //   tokens: 32*4096*1024 = 134,217,728 elements (fp32)
    //   mask  : 32*4096      =     131,072 elements (int32)
    const float* tokens;
    const int*   mask;
    if (in_sizes[0] > in_sizes[1]) {
        tokens = (const float*)d_in[0];
        mask   = (const int*)d_in[1];
    } else {
        tokens = (const float*)d_in[1];
        mask   = (const int*)d_in[0];
    }
    float* out = (float*)d_out;   // (32, 1024) fp32

    condensed_embracement_kernel<<<BS, 1024>>>(tokens, mask, out);
}